// round 6
// baseline (speedup 1.0000x reference)
#include <cuda_runtime.h>
#include <cuda_bf16.h>
#include <cstddef>
#include <cstdint>

#define NMAX 100000
#define EMAX 1700000
#define D 128
#define APAD 132   // padded bf16 row stride in smem

// ---------------------------------------------------------------------------
// Scratch (device-global, allocation-free per harness rules)
// ---------------------------------------------------------------------------
__device__ float g_h1[(size_t)NMAX * D];
__device__ float g_h2[(size_t)NMAX * D];
__device__ int   g_deg[2 * NMAX];
__device__ int   g_off[2 * NMAX];
__device__ int   g_cursor[2 * NMAX];
__device__ int   g_nbr[2 * EMAX];
__device__ int   g_aux[1024];
// bf16 hi/lo layer weight images: [layer][chunk][n_outcol][k]  (transposed)
__device__ unsigned short g_wth[4 * 128 * 128];
__device__ unsigned short g_wtl[4 * 128 * 128];
// bf16 hi/lo head weight images: [n_outcol(40)][k(256)]
__device__ unsigned short g_woth[40 * 256];
__device__ unsigned short g_wotl[40 * 256];

__device__ __forceinline__ unsigned short bfu(__nv_bfloat16 b) {
    return __bfloat16_as_ushort(b);
}

// mma.sync m16n8k16 bf16 (plain-target PTX; HMMA in SASS)
__device__ __forceinline__ void mma16816(float* c, const unsigned* a, const unsigned* b) {
    asm volatile(
        "mma.sync.aligned.m16n8k16.row.col.f32.bf16.bf16.f32 "
        "{%0,%1,%2,%3}, {%4,%5,%6,%7}, {%8,%9}, {%0,%1,%2,%3};"
        : "+f"(c[0]), "+f"(c[1]), "+f"(c[2]), "+f"(c[3])
        : "r"(a[0]), "r"(a[1]), "r"(a[2]), "r"(a[3]), "r"(b[0]), "r"(b[1]));
}

__device__ __forceinline__ void split_pack(float x, float y,
                                           unsigned& hp, unsigned& lp) {
    __nv_bfloat16 hx = __float2bfloat16(x);
    __nv_bfloat16 hy = __float2bfloat16(y);
    __nv_bfloat16 lx = __float2bfloat16(x - __bfloat162float(hx));
    __nv_bfloat16 ly = __float2bfloat16(y - __bfloat162float(hy));
    hp = (unsigned)bfu(hx) | ((unsigned)bfu(hy) << 16);
    lp = (unsigned)bfu(lx) | ((unsigned)bfu(ly) << 16);
}

// ---------------------------------------------------------------------------
// One-shot weight prep: layer weights (2 layers x {wl,wr}, transposed, hi/lo)
// + head weights (transposed [40][256], hi/lo)
// ---------------------------------------------------------------------------
__global__ void __launch_bounds__(256) prep_all_kernel(
    const float* __restrict__ wl1, const float* __restrict__ wr1,
    const float* __restrict__ wl2, const float* __restrict__ wr2,
    const float* __restrict__ w_out)
{
    int idx = blockIdx.x * 256 + threadIdx.x;   // 65536 + 10240 = 75776
    if (idx < 65536) {
        int layer = idx >> 15;
        int rem   = idx & 32767;
        int c     = rem >> 14;
        int nrow  = (rem >> 7) & 127;
        int k     = rem & 127;
        const float* w = layer ? (c ? wr2 : wl2) : (c ? wr1 : wl1);
        float v = __ldg(w + k * 128 + nrow);
        __nv_bfloat16 hb = __float2bfloat16(v);
        __nv_bfloat16 lb = __float2bfloat16(v - __bfloat162float(hb));
        int o = (layer * 2 + c) * 16384 + nrow * 128 + k;
        g_wth[o] = bfu(hb);
        g_wtl[o] = bfu(lb);
    } else if (idx < 75776) {
        int j = idx - 65536;         // 0..10239
        int nn = j >> 8;             // 0..39
        int k  = j & 255;
        float v = __ldg(w_out + k * 40 + nn);
        __nv_bfloat16 hb = __float2bfloat16(v);
        __nv_bfloat16 lb = __float2bfloat16(v - __bfloat162float(hb));
        g_woth[nn * 256 + k] = bfu(hb);
        g_wotl[nn * 256 + k] = bfu(lb);
    }
}

// ---------------------------------------------------------------------------
// Merged CSR build for both edge lists
// ---------------------------------------------------------------------------
__global__ void zero_both_kernel(int n) {
    int i = blockIdx.x * blockDim.x + threadIdx.x;
    int stride = gridDim.x * blockDim.x;
    for (int j = i; j < n; j += stride) { g_deg[j] = 0; g_deg[NMAX + j] = 0; }
}

__global__ void __launch_bounds__(256) count_both_kernel(
    const int* __restrict__ ei1, const int* __restrict__ ei2, int E1, int E2)
{
    int e = blockIdx.x * 256 + threadIdx.x;
    if (e < E1) atomicAdd(&g_deg[__ldg(ei1 + E1 + e)], 1);
    int e2 = e - E1;
    if (e2 >= 0 && e2 < E2) atomicAdd(&g_deg[NMAX + __ldg(ei2 + E2 + e2)], 1);
}

__global__ void __launch_bounds__(1024) scan1_kernel(int n) {
    __shared__ int s[1024];
    int a = blockIdx.y;
    int t = threadIdx.x;
    int i = blockIdx.x * 1024 + t;
    int v = (i < n) ? g_deg[a * NMAX + i] : 0;
    s[t] = v;
    __syncthreads();
#pragma unroll
    for (int d = 1; d < 1024; d <<= 1) {
        int add = (t >= d) ? s[t - d] : 0;
        __syncthreads();
        s[t] += add;
        __syncthreads();
    }
    if (i < n) g_off[a * NMAX + i] = s[t] - v;
    if (t == 1023) g_aux[a * 512 + blockIdx.x] = s[1023];
}

__global__ void __launch_bounds__(1024) scan2_kernel(int nb) {
    __shared__ int s[1024];
    int a = blockIdx.x;
    int t = threadIdx.x;
    int v = (t < nb) ? g_aux[a * 512 + t] : 0;
    s[t] = v;
    __syncthreads();
#pragma unroll
    for (int d = 1; d < 1024; d <<= 1) {
        int add = (t >= d) ? s[t - d] : 0;
        __syncthreads();
        s[t] += add;
        __syncthreads();
    }
    if (t < nb) g_aux[a * 512 + t] = s[t] - v;
}

__global__ void __launch_bounds__(256) scan3_kernel(int n) {
    int a = blockIdx.y;
    int i = blockIdx.x * 256 + threadIdx.x;
    if (i >= n) return;
    int o = g_off[a * NMAX + i] + g_aux[a * 512 + (i >> 10)];
    g_off[a * NMAX + i] = o;
    g_cursor[a * NMAX + i] = o;
}

__global__ void __launch_bounds__(256) fill_both_kernel(
    const int* __restrict__ ei1, const int* __restrict__ ei2, int E1, int E2)
{
    int e = blockIdx.x * 256 + threadIdx.x;
    if (e < E1) {
        int s = __ldg(ei1 + e);
        int d = __ldg(ei1 + E1 + e);
        int pos = atomicAdd(&g_cursor[d], 1);
        g_nbr[pos] = s;
    }
    int e2 = e - E1;
    if (e2 >= 0 && e2 < E2) {
        int s = __ldg(ei2 + e2);
        int d = __ldg(ei2 + E2 + e2);
        int pos = atomicAdd(&g_cursor[NMAX + d], 1);
        g_nbr[EMAX + pos] = s;
    }
}

// ---------------------------------------------------------------------------
// Fused SAGE layer (gather + HMMA GEMM):
// out = relu(mean_nbr(xin) @ wl + xin @ wr + bias)
// CTA: 64 rows x 128 cols, 8 warps = 2(M) x 4(N), warp tile 32x32.
// chunk0: A = gathered neighbor-mean (warp-per-row gather into bf16 hi/lo smem)
// chunk1: A = root rows of xin.  bf16 2-term split, 3 HMMA products, fp32 acc.
// ---------------------------------------------------------------------------
__global__ void __launch_bounds__(256) layer_fused_kernel(
    const float* __restrict__ xin, const float* __restrict__ bias,
    float* __restrict__ out, int n, int csr,
    const unsigned short* __restrict__ wth_base,
    const unsigned short* __restrict__ wtl_base)
{
    extern __shared__ unsigned short sm[];
    unsigned short* s_ah = sm;                       // 64 x APAD
    unsigned short* s_al = sm + 64 * APAD;
    unsigned short* s_wh = sm + 2 * 64 * APAD;       // 128 x APAD
    unsigned short* s_wl = s_wh + 128 * APAD;

    int tid = threadIdx.x, wid = tid >> 5, lane = tid & 31;
    int r0 = blockIdx.x * 64;
    int mrow = (wid & 1) * 32;
    int ncol = (wid >> 1) * 32;

    const int* off = g_off + csr * NMAX;
    const int* deg = g_deg + csr * NMAX;
    const int* nbr = g_nbr + csr * EMAX;

    float acc[2][4][4];
#pragma unroll
    for (int mt = 0; mt < 2; mt++)
#pragma unroll
        for (int nt = 0; nt < 4; nt++)
#pragma unroll
            for (int q = 0; q < 4; q++) acc[mt][nt][q] = 0.f;

    const float4* src4 = reinterpret_cast<const float4*>(xin);

    for (int chunk = 0; chunk < 2; chunk++) {
        if (chunk) __syncthreads();   // protect smem reuse

        // ---- stage W chunk (pre-split transposed images) ----
        {
            const uint2* gh = reinterpret_cast<const uint2*>(wth_base) + chunk * 4096;
            const uint2* gl = reinterpret_cast<const uint2*>(wtl_base) + chunk * 4096;
#pragma unroll
            for (int i = 0; i < 16; i++) {
                int j = tid + i * 256;        // 128 rows * 32 uint2
                int nrow = j >> 5, kk = (j & 31) * 4;
                int o = nrow * APAD + kk;
                *reinterpret_cast<uint2*>(s_wh + o) = __ldg(gh + j);
                *reinterpret_cast<uint2*>(s_wl + o) = __ldg(gl + j);
            }
        }

        if (chunk == 0) {
            // ---- gather: warp-per-row neighbor mean, bf16 split into smem ----
            for (int j = 0; j < 8; j++) {
                int row = wid * 8 + j;
                int gr = r0 + row;
                if (gr >= n) gr = n - 1;
                int st = __ldg(off + gr);
                int dg = __ldg(deg + gr);
                float4 a = make_float4(0.f, 0.f, 0.f, 0.f);
                int i = 0;
                for (; i + 4 <= dg; i += 4) {
                    int s0 = __ldg(nbr + st + i);
                    int s1 = __ldg(nbr + st + i + 1);
                    int s2 = __ldg(nbr + st + i + 2);
                    int s3 = __ldg(nbr + st + i + 3);
                    float4 v0 = __ldg(src4 + (size_t)s0 * 32 + lane);
                    float4 v1 = __ldg(src4 + (size_t)s1 * 32 + lane);
                    float4 v2 = __ldg(src4 + (size_t)s2 * 32 + lane);
                    float4 v3 = __ldg(src4 + (size_t)s3 * 32 + lane);
                    a.x += (v0.x + v1.x) + (v2.x + v3.x);
                    a.y += (v0.y + v1.y) + (v2.y + v3.y);
                    a.z += (v0.z + v1.z) + (v2.z + v3.z);
                    a.w += (v0.w + v1.w) + (v2.w + v3.w);
                }
                for (; i < dg; i++) {
                    int s0 = __ldg(nbr + st + i);
                    float4 v0 = __ldg(src4 + (size_t)s0 * 32 + lane);
                    a.x += v0.x; a.y += v0.y; a.z += v0.z; a.w += v0.w;
                }
                float inv = 1.0f / (float)max(dg, 1);
                a.x *= inv; a.y *= inv; a.z *= inv; a.w *= inv;
                unsigned hp0, lp0, hp1, lp1;
                split_pack(a.x, a.y, hp0, lp0);
                split_pack(a.z, a.w, hp1, lp1);
                int o = row * APAD + lane * 4;
                *reinterpret_cast<uint2*>(s_ah + o) = make_uint2(hp0, hp1);
                *reinterpret_cast<uint2*>(s_al + o) = make_uint2(lp0, lp1);
            }
        } else {
            // ---- stage root rows of xin ----
#pragma unroll
            for (int i = 0; i < 8; i++) {
                int f = tid + i * 256;          // 64 rows * 32 float4
                int row = f >> 5, k4 = f & 31;
                int gr = r0 + row;
                if (gr >= n) gr = n - 1;
                float4 v = __ldg(src4 + (size_t)gr * 32 + k4);
                unsigned hp0, lp0, hp1, lp1;
                split_pack(v.x, v.y, hp0, lp0);
                split_pack(v.z, v.w, hp1, lp1);
                int o = row * APAD + k4 * 4;
                *reinterpret_cast<uint2*>(s_ah + o) = make_uint2(hp0, hp1);
                *reinterpret_cast<uint2*>(s_al + o) = make_uint2(lp0, lp1);
            }
        }
        __syncthreads();

        // ---- compute: 8 k-steps of m16n8k16, 3 products ----
#pragma unroll
        for (int s = 0; s < 8; s++) {
            int kc = s * 16 + (lane & 3) * 2;
            unsigned bh[4][2], bl[4][2];
#pragma unroll
            for (int nt = 0; nt < 4; nt++) {
                int nn = ncol + nt * 8 + (lane >> 2);
                bh[nt][0] = *reinterpret_cast<unsigned*>(s_wh + nn * APAD + kc);
                bh[nt][1] = *reinterpret_cast<unsigned*>(s_wh + nn * APAD + kc + 8);
                bl[nt][0] = *reinterpret_cast<unsigned*>(s_wl + nn * APAD + kc);
                bl[nt][1] = *reinterpret_cast<unsigned*>(s_wl + nn * APAD + kc + 8);
            }
#pragma unroll
            for (int mt = 0; mt < 2; mt++) {
                int rr = mrow + mt * 16 + (lane >> 2);
                unsigned ah[4], al[4];
                ah[0] = *reinterpret_cast<unsigned*>(s_ah + rr * APAD + kc);
                ah[1] = *reinterpret_cast<unsigned*>(s_ah + (rr + 8) * APAD + kc);
                ah[2] = *reinterpret_cast<unsigned*>(s_ah + rr * APAD + kc + 8);
                ah[3] = *reinterpret_cast<unsigned*>(s_ah + (rr + 8) * APAD + kc + 8);
                al[0] = *reinterpret_cast<unsigned*>(s_al + rr * APAD + kc);
                al[1] = *reinterpret_cast<unsigned*>(s_al + (rr + 8) * APAD + kc);
                al[2] = *reinterpret_cast<unsigned*>(s_al + rr * APAD + kc + 8);
                al[3] = *reinterpret_cast<unsigned*>(s_al + (rr + 8) * APAD + kc + 8);
#pragma unroll
                for (int nt = 0; nt < 4; nt++) {
                    mma16816(acc[mt][nt], ah, bh[nt]);   // hi*hi
                    mma16816(acc[mt][nt], ah, bl[nt]);   // hi*lo
                    mma16816(acc[mt][nt], al, bh[nt]);   // lo*hi
                }
            }
        }
    }

    // ---- epilogue: bias + relu + store ----
#pragma unroll
    for (int mt = 0; mt < 2; mt++) {
#pragma unroll
        for (int nt = 0; nt < 4; nt++) {
            int col = ncol + nt * 8 + (lane & 3) * 2;
            float bx = __ldg(bias + col), by = __ldg(bias + col + 1);
            int row = r0 + mrow + mt * 16 + (lane >> 2);
            if (row < n) {
                float2 o;
                o.x = fmaxf(acc[mt][nt][0] + bx, 0.f);
                o.y = fmaxf(acc[mt][nt][1] + by, 0.f);
                *reinterpret_cast<float2*>(out + (size_t)row * 128 + col) = o;
            }
            if (row + 8 < n) {
                float2 o;
                o.x = fmaxf(acc[mt][nt][2] + bx, 0.f);
                o.y = fmaxf(acc[mt][nt][3] + by, 0.f);
                *reinterpret_cast<float2*>(out + (size_t)(row + 8) * 128 + col) = o;
            }
        }
    }
}

// ---------------------------------------------------------------------------
// HMMA head: out[row] = [h1,h2] @ w_out + b_out   (K=256, Ncls=40)
// CTA 256 thr = 8 warps x 16 rows = 128 rows. Warp: 5 n-tiles (n8), 16 k-steps.
// A fragments loaded from gmem fp32, split in registers; B from prepped images.
// ---------------------------------------------------------------------------
__global__ void __launch_bounds__(256) head_kernel(
    const float* __restrict__ b_out, float* __restrict__ out, int n)
{
    int tid = threadIdx.x, wid = tid >> 5, lane = tid & 31;
    int r0 = blockIdx.x * 128 + wid * 16;
    int rq = lane >> 2;
    int kc = (lane & 3) * 2;

    float acc[5][4];
#pragma unroll
    for (int nt = 0; nt < 5; nt++)
#pragma unroll
        for (int q = 0; q < 4; q++) acc[nt][q] = 0.f;

    int ra = r0 + rq;     if (ra >= n) ra = n - 1;
    int rb = r0 + rq + 8; if (rb >= n) rb = n - 1;

#pragma unroll
    for (int s = 0; s < 16; s++) {
        const float* hsrc = (s < 8) ? g_h1 : g_h2;
        int kk = ((s < 8) ? s * 16 : (s - 8) * 16) + kc;
        int kg = s * 16 + kc;    // global k for B images

        float2 v00 = *reinterpret_cast<const float2*>(hsrc + (size_t)ra * 128 + kk);
        float2 v10 = *reinterpret_cast<const float2*>(hsrc + (size_t)rb * 128 + kk);
        float2 v01 = *reinterpret_cast<const float2*>(hsrc + (size_t)ra * 128 + kk + 8);
        float2 v11 = *reinterpret_cast<const float2*>(hsrc + (size_t)rb * 128 + kk + 8);

        unsigned ah[4], al[4];
        split_pack(v00.x, v00.y, ah[0], al[0]);
        split_pack(v10.x, v10.y, ah[1], al[1]);
        split_pack(v01.x, v01.y, ah[2], al[2]);
        split_pack(v11.x, v11.y, ah[3], al[3]);

#pragma unroll
        for (int nt = 0; nt < 5; nt++) {
            int nn = nt * 8 + rq;
            unsigned bh[2], bl[2];
            bh[0] = *reinterpret_cast<const unsigned*>(g_woth + nn * 256 + kg);
            bh[1] = *reinterpret_cast<const unsigned*>(g_woth + nn * 256 + kg + 8);
            bl[0] = *reinterpret_cast<const unsigned*>(g_wotl + nn * 256 + kg);
            bl[1] = *reinterpret_cast<const unsigned*>(g_wotl + nn * 256 + kg + 8);
            mma16816(acc[nt], ah, bh);
            mma16816(acc[nt], ah, bl);
            mma16816(acc[nt], al, bh);
        }
    }

#pragma unroll
    for (int nt = 0; nt < 5; nt++) {
        int col = nt * 8 + (lane & 3) * 2;
        float bx = __ldg(b_out + col), by = __ldg(b_out + col + 1);
        int row = r0 + (lane >> 2);
        if (row < n) {
            float2 o = make_float2(acc[nt][0] + bx, acc[nt][1] + by);
            *reinterpret_cast<float2*>(out + (size_t)row * 40 + col) = o;
        }
        if (row + 8 < n) {
            float2 o = make_float2(acc[nt][2] + bx, acc[nt][3] + by);
            *reinterpret_cast<float2*>(out + (size_t)(row + 8) * 40 + col) = o;
        }
    }
}

// ---------------------------------------------------------------------------
extern "C" void kernel_launch(void* const* d_in, const int* in_sizes, int n_in,
                              void* d_out, int out_size)
{
    const float* x     = (const float*)d_in[0];
    const int*   ei1   = (const int*)d_in[1];
    const int*   ei2   = (const int*)d_in[2];
    const float* wl1   = (const float*)d_in[3];
    const float* wr1   = (const float*)d_in[4];
    const float* b1    = (const float*)d_in[5];
    const float* wl2   = (const float*)d_in[6];
    const float* wr2   = (const float*)d_in[7];
    const float* b2    = (const float*)d_in[8];
    const float* w_out = (const float*)d_in[9];
    const float* b_out = (const float*)d_in[10];

    int n  = in_sizes[0] / D;
    int E1 = in_sizes[1] / 2;
    int E2 = in_sizes[2] / 2;
    int n_rows_out = out_size / 40;

    void *p_h1 = nullptr, *p_h2 = nullptr, *p_wth = nullptr, *p_wtl = nullptr;
    cudaGetSymbolAddress(&p_h1, g_h1);
    cudaGetSymbolAddress(&p_h2, g_h2);
    cudaGetSymbolAddress(&p_wth, g_wth);
    cudaGetSymbolAddress(&p_wtl, g_wtl);
    float* h1 = (float*)p_h1;
    float* h2 = (float*)p_h2;
    const unsigned short* wth = (const unsigned short*)p_wth;
    const unsigned short* wtl = (const unsigned short*)p_wtl;

    const int LAYER_SMEM = (2 * 64 + 2 * 128) * APAD * 2;   // 101376 B
    cudaFuncSetAttribute(layer_fused_kernel,
                         cudaFuncAttributeMaxDynamicSharedMemorySize, LAYER_SMEM);

    int nb_scan = (n + 1023) / 1024;
    int Emax = (E1 > E2) ? E1 : E2;
    (void)Emax;

    // ---- weight prep (all layers + head) ----
    prep_all_kernel<<<296, 256>>>(wl1, wr1, wl2, wr2, w_out);

    // ---- merged CSR build for both edge lists ----
    zero_both_kernel<<<256, 256>>>(n);
    count_both_kernel<<<(E1 + E2 + 255) / 256, 256>>>(ei1, ei2, E1, E2);
    scan1_kernel<<<dim3(nb_scan, 2), 1024>>>(n);
    scan2_kernel<<<2, 1024>>>(nb_scan);
    scan3_kernel<<<dim3((n + 255) / 256, 2), 256>>>(n);
    fill_both_kernel<<<(E1 + E2 + 255) / 256, 256>>>(ei1, ei2, E1, E2);

    int layer_blocks = (n + 63) / 64;

    // ---- layer 1 (fused gather + GEMM) ----
    layer_fused_kernel<<<layer_blocks, 256, LAYER_SMEM>>>(
        x, b1, h1, n, 0, wth, wtl);

    // ---- layer 2 ----
    layer_fused_kernel<<<layer_blocks, 256, LAYER_SMEM>>>(
        h1, b2, h2, n, 1, wth + 32768, wtl + 32768);

    // ---- JK cat + HMMA head ----
    head_kernel<<<(n_rows_out + 127) / 128, 256>>>(b_out, (float*)d_out, n_rows_out);
}

// round 7
// speedup vs baseline: 1.2336x; 1.2336x over previous
#include <cuda_runtime.h>
#include <cuda_bf16.h>
#include <cstddef>
#include <cstdint>

#define NMAX 100000
#define EMAX 1700000
#define D 128
#define APAD 132   // padded bf16 row stride in smem

// ---------------------------------------------------------------------------
// Scratch (device-global, allocation-free per harness rules)
// ---------------------------------------------------------------------------
__device__ float g_agg[(size_t)NMAX * D];
__device__ float g_h1[(size_t)NMAX * D];
__device__ float g_h2[(size_t)NMAX * D];
__device__ int   g_deg[2 * NMAX];
__device__ int   g_off[2 * NMAX];
__device__ int   g_cursor[2 * NMAX];
__device__ int   g_nbr[2 * EMAX];
__device__ int   g_aux[1024];
// bf16 hi/lo layer weight images: [layer][chunk][n_outcol][k]  (transposed)
__device__ unsigned short g_wth[4 * 128 * 128];
__device__ unsigned short g_wtl[4 * 128 * 128];
// bf16 hi/lo head weight images: [n_outcol(40)][k(256)]
__device__ unsigned short g_woth[40 * 256];
__device__ unsigned short g_wotl[40 * 256];

__device__ __forceinline__ unsigned short bfu(__nv_bfloat16 b) {
    return __bfloat16_as_ushort(b);
}

// mma.sync m16n8k16 bf16 (plain-target PTX; HMMA in SASS)
__device__ __forceinline__ void mma16816(float* c, const unsigned* a, const unsigned* b) {
    asm volatile(
        "mma.sync.aligned.m16n8k16.row.col.f32.bf16.bf16.f32 "
        "{%0,%1,%2,%3}, {%4,%5,%6,%7}, {%8,%9}, {%0,%1,%2,%3};"
        : "+f"(c[0]), "+f"(c[1]), "+f"(c[2]), "+f"(c[3])
        : "r"(a[0]), "r"(a[1]), "r"(a[2]), "r"(a[3]), "r"(b[0]), "r"(b[1]));
}

__device__ __forceinline__ void split_pack(float x, float y,
                                           unsigned& hp, unsigned& lp) {
    __nv_bfloat16 hx = __float2bfloat16(x);
    __nv_bfloat16 hy = __float2bfloat16(y);
    __nv_bfloat16 lx = __float2bfloat16(x - __bfloat162float(hx));
    __nv_bfloat16 ly = __float2bfloat16(y - __bfloat162float(hy));
    hp = (unsigned)bfu(hx) | ((unsigned)bfu(hy) << 16);
    lp = (unsigned)bfu(lx) | ((unsigned)bfu(ly) << 16);
}

// ---------------------------------------------------------------------------
// One-shot weight prep: layer weights (2 layers x {wl,wr}, transposed, hi/lo)
// + head weights (transposed [40][256], hi/lo)
// ---------------------------------------------------------------------------
__global__ void __launch_bounds__(256) prep_all_kernel(
    const float* __restrict__ wl1, const float* __restrict__ wr1,
    const float* __restrict__ wl2, const float* __restrict__ wr2,
    const float* __restrict__ w_out)
{
    int idx = blockIdx.x * 256 + threadIdx.x;   // 65536 + 10240 = 75776
    if (idx < 65536) {
        int layer = idx >> 15;
        int rem   = idx & 32767;
        int c     = rem >> 14;
        int nrow  = (rem >> 7) & 127;
        int k     = rem & 127;
        const float* w = layer ? (c ? wr2 : wl2) : (c ? wr1 : wl1);
        float v = __ldg(w + k * 128 + nrow);
        __nv_bfloat16 hb = __float2bfloat16(v);
        __nv_bfloat16 lb = __float2bfloat16(v - __bfloat162float(hb));
        int o = (layer * 2 + c) * 16384 + nrow * 128 + k;
        g_wth[o] = bfu(hb);
        g_wtl[o] = bfu(lb);
    } else if (idx < 75776) {
        int j = idx - 65536;         // 0..10239
        int nn = j >> 8;             // 0..39
        int k  = j & 255;
        float v = __ldg(w_out + k * 40 + nn);
        __nv_bfloat16 hb = __float2bfloat16(v);
        __nv_bfloat16 lb = __float2bfloat16(v - __bfloat162float(hb));
        g_woth[nn * 256 + k] = bfu(hb);
        g_wotl[nn * 256 + k] = bfu(lb);
    }
}

// ---------------------------------------------------------------------------
// Merged CSR build for both edge lists
// ---------------------------------------------------------------------------
__global__ void zero_both_kernel(int n) {
    int i = blockIdx.x * blockDim.x + threadIdx.x;
    int stride = gridDim.x * blockDim.x;
    for (int j = i; j < n; j += stride) { g_deg[j] = 0; g_deg[NMAX + j] = 0; }
}

__global__ void __launch_bounds__(256) count_both_kernel(
    const int* __restrict__ ei1, const int* __restrict__ ei2, int E1, int E2)
{
    int e = blockIdx.x * 256 + threadIdx.x;
    if (e < E1) atomicAdd(&g_deg[__ldg(ei1 + E1 + e)], 1);
    int e2 = e - E1;
    if (e2 >= 0 && e2 < E2) atomicAdd(&g_deg[NMAX + __ldg(ei2 + E2 + e2)], 1);
}

__global__ void __launch_bounds__(1024) scan1_kernel(int n) {
    __shared__ int s[1024];
    int a = blockIdx.y;
    int t = threadIdx.x;
    int i = blockIdx.x * 1024 + t;
    int v = (i < n) ? g_deg[a * NMAX + i] : 0;
    s[t] = v;
    __syncthreads();
#pragma unroll
    for (int d = 1; d < 1024; d <<= 1) {
        int add = (t >= d) ? s[t - d] : 0;
        __syncthreads();
        s[t] += add;
        __syncthreads();
    }
    if (i < n) g_off[a * NMAX + i] = s[t] - v;
    if (t == 1023) g_aux[a * 512 + blockIdx.x] = s[1023];
}

__global__ void __launch_bounds__(1024) scan2_kernel(int nb) {
    __shared__ int s[1024];
    int a = blockIdx.x;
    int t = threadIdx.x;
    int v = (t < nb) ? g_aux[a * 512 + t] : 0;
    s[t] = v;
    __syncthreads();
#pragma unroll
    for (int d = 1; d < 1024; d <<= 1) {
        int add = (t >= d) ? s[t - d] : 0;
        __syncthreads();
        s[t] += add;
        __syncthreads();
    }
    if (t < nb) g_aux[a * 512 + t] = s[t] - v;
}

__global__ void __launch_bounds__(256) scan3_kernel(int n) {
    int a = blockIdx.y;
    int i = blockIdx.x * 256 + threadIdx.x;
    if (i >= n) return;
    int o = g_off[a * NMAX + i] + g_aux[a * 512 + (i >> 10)];
    g_off[a * NMAX + i] = o;
    g_cursor[a * NMAX + i] = o;
}

__global__ void __launch_bounds__(256) fill_both_kernel(
    const int* __restrict__ ei1, const int* __restrict__ ei2, int E1, int E2)
{
    int e = blockIdx.x * 256 + threadIdx.x;
    if (e < E1) {
        int s = __ldg(ei1 + e);
        int d = __ldg(ei1 + E1 + e);
        int pos = atomicAdd(&g_cursor[d], 1);
        g_nbr[pos] = s;
    }
    int e2 = e - E1;
    if (e2 >= 0 && e2 < E2) {
        int s = __ldg(ei2 + e2);
        int d = __ldg(ei2 + E2 + e2);
        int pos = atomicAdd(&g_cursor[NMAX + d], 1);
        g_nbr[EMAX + pos] = s;
    }
}

// ---------------------------------------------------------------------------
// Gather-mean: warp per node, high occupancy (standalone for latency hiding)
// ---------------------------------------------------------------------------
__global__ void __launch_bounds__(256) gather_kernel(
    const float* __restrict__ feat, int n, int csr)
{
    int v = (blockIdx.x * 256 + threadIdx.x) >> 5;
    int lane = threadIdx.x & 31;
    if (v >= n) return;
    int start = __ldg(g_off + csr * NMAX + v);
    int deg   = __ldg(g_deg + csr * NMAX + v);
    const int* nbr = g_nbr + csr * EMAX;
    const float4* f4 = reinterpret_cast<const float4*>(feat);
    float4 acc = make_float4(0.f, 0.f, 0.f, 0.f);
    int i = 0;
    for (; i + 4 <= deg; i += 4) {
        int s0 = __ldg(nbr + start + i);
        int s1 = __ldg(nbr + start + i + 1);
        int s2 = __ldg(nbr + start + i + 2);
        int s3 = __ldg(nbr + start + i + 3);
        float4 a = __ldg(f4 + (size_t)s0 * 32 + lane);
        float4 b = __ldg(f4 + (size_t)s1 * 32 + lane);
        float4 c = __ldg(f4 + (size_t)s2 * 32 + lane);
        float4 d = __ldg(f4 + (size_t)s3 * 32 + lane);
        acc.x += (a.x + b.x) + (c.x + d.x);
        acc.y += (a.y + b.y) + (c.y + d.y);
        acc.z += (a.z + b.z) + (c.z + d.z);
        acc.w += (a.w + b.w) + (c.w + d.w);
    }
    for (; i < deg; i++) {
        int s0 = __ldg(nbr + start + i);
        float4 a = __ldg(f4 + (size_t)s0 * 32 + lane);
        acc.x += a.x; acc.y += a.y; acc.z += a.z; acc.w += a.w;
    }
    float inv = 1.0f / (float)max(deg, 1);
    acc.x *= inv; acc.y *= inv; acc.z *= inv; acc.w *= inv;
    reinterpret_cast<float4*>(g_agg)[(size_t)v * 32 + lane] = acc;
}

// ---------------------------------------------------------------------------
// HMMA SAGE layer: out = relu(agg @ wl + xin @ wr + bias)
// CTA: 64 rows x 128 cols. 8 warps = 2(M) x 4(N); warp tile 32x32.
// bf16 2-term split, 3 products, fp32 accumulate.
// ---------------------------------------------------------------------------
__global__ void __launch_bounds__(256) layer_mma_kernel(
    const float* __restrict__ xin, const float* __restrict__ bias,
    float* __restrict__ out, int n,
    const unsigned short* __restrict__ wth_base,
    const unsigned short* __restrict__ wtl_base)
{
    extern __shared__ unsigned short sm[];
    unsigned short* s_ah = sm;                       // 64 x APAD
    unsigned short* s_al = sm + 64 * APAD;
    unsigned short* s_wh = sm + 2 * 64 * APAD;       // 128 x APAD
    unsigned short* s_wl = s_wh + 128 * APAD;

    int tid = threadIdx.x, wid = tid >> 5, lane = tid & 31;
    int r0 = blockIdx.x * 64;
    int mrow = (wid & 1) * 32;
    int ncol = (wid >> 1) * 32;

    float acc[2][4][4];
#pragma unroll
    for (int mt = 0; mt < 2; mt++)
#pragma unroll
        for (int nt = 0; nt < 4; nt++)
#pragma unroll
            for (int q = 0; q < 4; q++) acc[mt][nt][q] = 0.f;

    for (int chunk = 0; chunk < 2; chunk++) {
        if (chunk) __syncthreads();   // protect smem reuse

        // ---- stage A (64 rows), fp32 -> bf16 hi/lo split ----
        const float4* src = (chunk == 0) ? reinterpret_cast<const float4*>(g_agg)
                                         : reinterpret_cast<const float4*>(xin);
#pragma unroll
        for (int i = 0; i < 8; i++) {
            int f = tid + i * 256;          // 64 rows * 32 float4
            int row = f >> 5, k4 = f & 31;
            int gr = r0 + row;
            if (gr >= n) gr = n - 1;
            float4 v = __ldg(src + (size_t)gr * 32 + k4);
            unsigned hp0, lp0, hp1, lp1;
            split_pack(v.x, v.y, hp0, lp0);
            split_pack(v.z, v.w, hp1, lp1);
            int o = row * APAD + k4 * 4;
            *reinterpret_cast<uint2*>(s_ah + o) = make_uint2(hp0, hp1);
            *reinterpret_cast<uint2*>(s_al + o) = make_uint2(lp0, lp1);
        }

        // ---- stage W chunk (pre-split transposed images) ----
        {
            const uint2* gh = reinterpret_cast<const uint2*>(wth_base) + chunk * 4096;
            const uint2* gl = reinterpret_cast<const uint2*>(wtl_base) + chunk * 4096;
#pragma unroll
            for (int i = 0; i < 16; i++) {
                int j = tid + i * 256;        // 128 rows * 32 uint2
                int nrow = j >> 5, kk = (j & 31) * 4;
                int o = nrow * APAD + kk;
                *reinterpret_cast<uint2*>(s_wh + o) = __ldg(gh + j);
                *reinterpret_cast<uint2*>(s_wl + o) = __ldg(gl + j);
            }
        }
        __syncthreads();

        // ---- compute: 8 k-steps of m16n8k16, 3 products ----
#pragma unroll
        for (int s = 0; s < 8; s++) {
            int kc = s * 16 + (lane & 3) * 2;
            unsigned bh[4][2], bl[4][2];
#pragma unroll
            for (int nt = 0; nt < 4; nt++) {
                int nn = ncol + nt * 8 + (lane >> 2);
                bh[nt][0] = *reinterpret_cast<unsigned*>(s_wh + nn * APAD + kc);
                bh[nt][1] = *reinterpret_cast<unsigned*>(s_wh + nn * APAD + kc + 8);
                bl[nt][0] = *reinterpret_cast<unsigned*>(s_wl + nn * APAD + kc);
                bl[nt][1] = *reinterpret_cast<unsigned*>(s_wl + nn * APAD + kc + 8);
            }
#pragma unroll
            for (int mt = 0; mt < 2; mt++) {
                int rr = mrow + mt * 16 + (lane >> 2);
                unsigned ah[4], al[4];
                ah[0] = *reinterpret_cast<unsigned*>(s_ah + rr * APAD + kc);
                ah[1] = *reinterpret_cast<unsigned*>(s_ah + (rr + 8) * APAD + kc);
                ah[2] = *reinterpret_cast<unsigned*>(s_ah + rr * APAD + kc + 8);
                ah[3] = *reinterpret_cast<unsigned*>(s_ah + (rr + 8) * APAD + kc + 8);
                al[0] = *reinterpret_cast<unsigned*>(s_al + rr * APAD + kc);
                al[1] = *reinterpret_cast<unsigned*>(s_al + (rr + 8) * APAD + kc);
                al[2] = *reinterpret_cast<unsigned*>(s_al + rr * APAD + kc + 8);
                al[3] = *reinterpret_cast<unsigned*>(s_al + (rr + 8) * APAD + kc + 8);
#pragma unroll
                for (int nt = 0; nt < 4; nt++) {
                    mma16816(acc[mt][nt], ah, bh[nt]);   // hi*hi
                    mma16816(acc[mt][nt], ah, bl[nt]);   // hi*lo
                    mma16816(acc[mt][nt], al, bh[nt]);   // lo*hi
                }
            }
        }
    }

    // ---- epilogue: bias + relu + store ----
#pragma unroll
    for (int mt = 0; mt < 2; mt++) {
#pragma unroll
        for (int nt = 0; nt < 4; nt++) {
            int col = ncol + nt * 8 + (lane & 3) * 2;
            float bx = __ldg(bias + col), by = __ldg(bias + col + 1);
            int row = r0 + mrow + mt * 16 + (lane >> 2);
            if (row < n) {
                float2 o;
                o.x = fmaxf(acc[mt][nt][0] + bx, 0.f);
                o.y = fmaxf(acc[mt][nt][1] + by, 0.f);
                *reinterpret_cast<float2*>(out + (size_t)row * 128 + col) = o;
            }
            if (row + 8 < n) {
                float2 o;
                o.x = fmaxf(acc[mt][nt][2] + bx, 0.f);
                o.y = fmaxf(acc[mt][nt][3] + by, 0.f);
                *reinterpret_cast<float2*>(out + (size_t)(row + 8) * 128 + col) = o;
            }
        }
    }
}

// ---------------------------------------------------------------------------
// HMMA head: out[row] = [h1,h2] @ w_out + b_out   (K=256, Ncls=40)
// CTA 256 thr = 8 warps x 16 rows = 128 rows. Warp: 5 n-tiles (n8), 16 k-steps.
// ---------------------------------------------------------------------------
__global__ void __launch_bounds__(256) head_kernel(
    const float* __restrict__ b_out, float* __restrict__ out, int n)
{
    int tid = threadIdx.x, wid = tid >> 5, lane = tid & 31;
    int r0 = blockIdx.x * 128 + wid * 16;
    int rq = lane >> 2;
    int kc = (lane & 3) * 2;

    float acc[5][4];
#pragma unroll
    for (int nt = 0; nt < 5; nt++)
#pragma unroll
        for (int q = 0; q < 4; q++) acc[nt][q] = 0.f;

    int ra = r0 + rq;     if (ra >= n) ra = n - 1;
    int rb = r0 + rq + 8; if (rb >= n) rb = n - 1;

#pragma unroll
    for (int s = 0; s < 16; s++) {
        const float* hsrc = (s < 8) ? g_h1 : g_h2;
        int kk = ((s < 8) ? s * 16 : (s - 8) * 16) + kc;
        int kg = s * 16 + kc;    // global k for B images

        float2 v00 = *reinterpret_cast<const float2*>(hsrc + (size_t)ra * 128 + kk);
        float2 v10 = *reinterpret_cast<const float2*>(hsrc + (size_t)rb * 128 + kk);
        float2 v01 = *reinterpret_cast<const float2*>(hsrc + (size_t)ra * 128 + kk + 8);
        float2 v11 = *reinterpret_cast<const float2*>(hsrc + (size_t)rb * 128 + kk + 8);

        unsigned ah[4], al[4];
        split_pack(v00.x, v00.y, ah[0], al[0]);
        split_pack(v10.x, v10.y, ah[1], al[1]);
        split_pack(v01.x, v01.y, ah[2], al[2]);
        split_pack(v11.x, v11.y, ah[3], al[3]);

#pragma unroll
        for (int nt = 0; nt < 5; nt++) {
            int nn = nt * 8 + rq;
            unsigned bh[2], bl[2];
            bh[0] = *reinterpret_cast<const unsigned*>(g_woth + nn * 256 + kg);
            bh[1] = *reinterpret_cast<const unsigned*>(g_woth + nn * 256 + kg + 8);
            bl[0] = *reinterpret_cast<const unsigned*>(g_wotl + nn * 256 + kg);
            bl[1] = *reinterpret_cast<const unsigned*>(g_wotl + nn * 256 + kg + 8);
            mma16816(acc[nt], ah, bh);
            mma16816(acc[nt], ah, bl);
            mma16816(acc[nt], al, bh);
        }
    }

#pragma unroll
    for (int nt = 0; nt < 5; nt++) {
        int col = nt * 8 + (lane & 3) * 2;
        float bx = __ldg(b_out + col), by = __ldg(b_out + col + 1);
        int row = r0 + (lane >> 2);
        if (row < n) {
            float2 o = make_float2(acc[nt][0] + bx, acc[nt][1] + by);
            *reinterpret_cast<float2*>(out + (size_t)row * 40 + col) = o;
        }
        if (row + 8 < n) {
            float2 o = make_float2(acc[nt][2] + bx, acc[nt][3] + by);
            *reinterpret_cast<float2*>(out + (size_t)(row + 8) * 40 + col) = o;
        }
    }
}

// ---------------------------------------------------------------------------
extern "C" void kernel_launch(void* const* d_in, const int* in_sizes, int n_in,
                              void* d_out, int out_size)
{
    const float* x     = (const float*)d_in[0];
    const int*   ei1   = (const int*)d_in[1];
    const int*   ei2   = (const int*)d_in[2];
    const float* wl1   = (const float*)d_in[3];
    const float* wr1   = (const float*)d_in[4];
    const float* b1    = (const float*)d_in[5];
    const float* wl2   = (const float*)d_in[6];
    const float* wr2   = (const float*)d_in[7];
    const float* b2    = (const float*)d_in[8];
    const float* w_out = (const float*)d_in[9];
    const float* b_out = (const float*)d_in[10];

    int n  = in_sizes[0] / D;
    int E1 = in_sizes[1] / 2;
    int E2 = in_sizes[2] / 2;
    int n_rows_out = out_size / 40;

    void *p_h1 = nullptr, *p_h2 = nullptr, *p_wth = nullptr, *p_wtl = nullptr;
    cudaGetSymbolAddress(&p_h1, g_h1);
    cudaGetSymbolAddress(&p_h2, g_h2);
    cudaGetSymbolAddress(&p_wth, g_wth);
    cudaGetSymbolAddress(&p_wtl, g_wtl);
    float* h1 = (float*)p_h1;
    float* h2 = (float*)p_h2;
    const unsigned short* wth = (const unsigned short*)p_wth;
    const unsigned short* wtl = (const unsigned short*)p_wtl;

    const int LAYER_SMEM = (2 * 64 + 2 * 128) * APAD * 2;   // 101376 B
    cudaFuncSetAttribute(layer_mma_kernel,
                         cudaFuncAttributeMaxDynamicSharedMemorySize, LAYER_SMEM);

    int nb_scan = (n + 1023) / 1024;

    // ---- weight prep (all layers + head) ----
    prep_all_kernel<<<296, 256>>>(wl1, wr1, wl2, wr2, w_out);

    // ---- merged CSR build for both edge lists ----
    zero_both_kernel<<<256, 256>>>(n);
    count_both_kernel<<<(E1 + E2 + 255) / 256, 256>>>(ei1, ei2, E1, E2);
    scan1_kernel<<<dim3(nb_scan, 2), 1024>>>(n);
    scan2_kernel<<<2, 1024>>>(nb_scan);
    scan3_kernel<<<dim3((n + 255) / 256, 2), 256>>>(n);
    fill_both_kernel<<<(E1 + E2 + 255) / 256, 256>>>(ei1, ei2, E1, E2);

    int layer_blocks = (n + 63) / 64;
    int gather_blocks = (n * 32 + 255) / 256;

    // ---- layer 1 ----
    gather_kernel<<<gather_blocks, 256>>>(x, n, 0);
    layer_mma_kernel<<<layer_blocks, 256, LAYER_SMEM>>>(x, b1, h1, n, wth, wtl);

    // ---- layer 2 ----
    gather_kernel<<<gather_blocks, 256>>>(h1, n, 1);
    layer_mma_kernel<<<layer_blocks, 256, LAYER_SMEM>>>(h1, b2, h2, n,
                                                        wth + 32768, wtl + 32768);

    // ---- JK cat + HMMA head ----
    head_kernel<<<(n_rows_out + 127) / 128, 256>>>(b_out, (float*)d_out, n_rows_out);
}

// round 8
// speedup vs baseline: 1.4861x; 1.2047x over previous
#include <cuda_runtime.h>
#include <cuda_bf16.h>
#include <cstddef>
#include <cstdint>

#define NMAX 100000
#define EMAX 1700000
#define D 128
#define APAD 132   // padded bf16 row stride in smem (main GEMM)
#define HPAD 264   // padded bf16 row stride (head phase, K=256)

// ---------------------------------------------------------------------------
// Scratch (device-global, allocation-free per harness rules)
// ---------------------------------------------------------------------------
__device__ float g_agg[(size_t)NMAX * D];
__device__ float g_h1[(size_t)NMAX * D];
__device__ unsigned short g_h1b[(size_t)NMAX * D];   // bf16 copy of h1
__device__ int   g_deg[2 * NMAX];
__device__ int   g_off[2 * NMAX];
__device__ int   g_cursor[2 * NMAX];
__device__ int   g_nbr[2 * EMAX];
__device__ int   g_aux[1024];
// bf16 hi/lo layer weight images: [layer][chunk][n_outcol][k]  (transposed)
__device__ unsigned short g_wth[4 * 128 * 128];
__device__ unsigned short g_wtl[4 * 128 * 128];
// bf16 hi/lo head weight images: [n_outcol(40)][k(256)]
__device__ unsigned short g_woth[40 * 256];
__device__ unsigned short g_wotl[40 * 256];

__device__ __forceinline__ unsigned short bfu(__nv_bfloat16 b) {
    return __bfloat16_as_ushort(b);
}

// mma.sync m16n8k16 bf16 (plain-target PTX; HMMA in SASS)
__device__ __forceinline__ void mma16816(float* c, const unsigned* a, const unsigned* b) {
    asm volatile(
        "mma.sync.aligned.m16n8k16.row.col.f32.bf16.bf16.f32 "
        "{%0,%1,%2,%3}, {%4,%5,%6,%7}, {%8,%9}, {%0,%1,%2,%3};"
        : "+f"(c[0]), "+f"(c[1]), "+f"(c[2]), "+f"(c[3])
        : "r"(a[0]), "r"(a[1]), "r"(a[2]), "r"(a[3]), "r"(b[0]), "r"(b[1]));
}

__device__ __forceinline__ void split_pack(float x, float y,
                                           unsigned& hp, unsigned& lp) {
    __nv_bfloat16 hx = __float2bfloat16(x);
    __nv_bfloat16 hy = __float2bfloat16(y);
    __nv_bfloat16 lx = __float2bfloat16(x - __bfloat162float(hx));
    __nv_bfloat16 ly = __float2bfloat16(y - __bfloat162float(hy));
    hp = (unsigned)bfu(hx) | ((unsigned)bfu(hy) << 16);
    lp = (unsigned)bfu(lx) | ((unsigned)bfu(ly) << 16);
}

// ---------------------------------------------------------------------------
// prep (weights split/transpose) + zero degrees, one kernel
// ---------------------------------------------------------------------------
__global__ void __launch_bounds__(256) prep_zero_kernel(
    const float* __restrict__ wl1, const float* __restrict__ wr1,
    const float* __restrict__ wl2, const float* __restrict__ wr2,
    const float* __restrict__ w_out)
{
    int idx = blockIdx.x * 256 + threadIdx.x;   // grid = 296*256 = 75776
    for (int j = idx; j < 2 * NMAX; j += 75776) g_deg[j] = 0;
    if (idx < 65536) {
        int layer = idx >> 15;
        int rem   = idx & 32767;
        int c     = rem >> 14;
        int nrow  = (rem >> 7) & 127;
        int k     = rem & 127;
        const float* w = layer ? (c ? wr2 : wl2) : (c ? wr1 : wl1);
        float v = __ldg(w + k * 128 + nrow);
        __nv_bfloat16 hb = __float2bfloat16(v);
        __nv_bfloat16 lb = __float2bfloat16(v - __bfloat162float(hb));
        int o = (layer * 2 + c) * 16384 + nrow * 128 + k;
        g_wth[o] = bfu(hb);
        g_wtl[o] = bfu(lb);
    } else if (idx < 75776) {
        int j = idx - 65536;         // 0..10239
        int nn = j >> 8;             // 0..39
        int k  = j & 255;
        float v = __ldg(w_out + k * 40 + nn);
        __nv_bfloat16 hb = __float2bfloat16(v);
        __nv_bfloat16 lb = __float2bfloat16(v - __bfloat162float(hb));
        g_woth[nn * 256 + k] = bfu(hb);
        g_wotl[nn * 256 + k] = bfu(lb);
    }
}

// ---------------------------------------------------------------------------
// Merged CSR build for both edge lists
// ---------------------------------------------------------------------------
__global__ void __launch_bounds__(256) count_both_kernel(
    const int* __restrict__ ei1, const int* __restrict__ ei2, int E1, int E2)
{
    int e = blockIdx.x * 256 + threadIdx.x;
    if (e < E1) atomicAdd(&g_deg[__ldg(ei1 + E1 + e)], 1);
    int e2 = e - E1;
    if (e2 >= 0 && e2 < E2) atomicAdd(&g_deg[NMAX + __ldg(ei2 + E2 + e2)], 1);
}

__global__ void __launch_bounds__(1024) scan1_kernel(int n) {
    __shared__ int s[1024];
    int a = blockIdx.y;
    int t = threadIdx.x;
    int i = blockIdx.x * 1024 + t;
    int v = (i < n) ? g_deg[a * NMAX + i] : 0;
    s[t] = v;
    __syncthreads();
#pragma unroll
    for (int d = 1; d < 1024; d <<= 1) {
        int add = (t >= d) ? s[t - d] : 0;
        __syncthreads();
        s[t] += add;
        __syncthreads();
    }
    if (i < n) g_off[a * NMAX + i] = s[t] - v;
    if (t == 1023) g_aux[a * 512 + blockIdx.x] = s[1023];
}

__global__ void __launch_bounds__(1024) scan2_kernel(int nb) {
    __shared__ int s[1024];
    int a = blockIdx.x;
    int t = threadIdx.x;
    int v = (t < nb) ? g_aux[a * 512 + t] : 0;
    s[t] = v;
    __syncthreads();
#pragma unroll
    for (int d = 1; d < 1024; d <<= 1) {
        int add = (t >= d) ? s[t - d] : 0;
        __syncthreads();
        s[t] += add;
        __syncthreads();
    }
    if (t < nb) g_aux[a * 512 + t] = s[t] - v;
}

__global__ void __launch_bounds__(256) scan3_kernel(int n) {
    int a = blockIdx.y;
    int i = blockIdx.x * 256 + threadIdx.x;
    if (i >= n) return;
    int o = g_off[a * NMAX + i] + g_aux[a * 512 + (i >> 10)];
    g_off[a * NMAX + i] = o;
    g_cursor[a * NMAX + i] = o;
}

__global__ void __launch_bounds__(256) fill_both_kernel(
    const int* __restrict__ ei1, const int* __restrict__ ei2, int E1, int E2)
{
    int e = blockIdx.x * 256 + threadIdx.x;
    if (e < E1) {
        int s = __ldg(ei1 + e);
        int d = __ldg(ei1 + E1 + e);
        int pos = atomicAdd(&g_cursor[d], 1);
        g_nbr[pos] = s;
    }
    int e2 = e - E1;
    if (e2 >= 0 && e2 < E2) {
        int s = __ldg(ei2 + e2);
        int d = __ldg(ei2 + E2 + e2);
        int pos = atomicAdd(&g_cursor[NMAX + d], 1);
        g_nbr[EMAX + pos] = s;
    }
}

// ---------------------------------------------------------------------------
// Gather-mean fp32 (layer 1): warp per node
// ---------------------------------------------------------------------------
__global__ void __launch_bounds__(256) gather_f32_kernel(
    const float* __restrict__ feat, int n)
{
    int v = (blockIdx.x * 256 + threadIdx.x) >> 5;
    int lane = threadIdx.x & 31;
    if (v >= n) return;
    int start = __ldg(g_off + v);
    int deg   = __ldg(g_deg + v);
    const float4* f4 = reinterpret_cast<const float4*>(feat);
    float4 acc = make_float4(0.f, 0.f, 0.f, 0.f);
    int i = 0;
    for (; i + 4 <= deg; i += 4) {
        int s0 = __ldg(g_nbr + start + i);
        int s1 = __ldg(g_nbr + start + i + 1);
        int s2 = __ldg(g_nbr + start + i + 2);
        int s3 = __ldg(g_nbr + start + i + 3);
        float4 a = __ldg(f4 + (size_t)s0 * 32 + lane);
        float4 b = __ldg(f4 + (size_t)s1 * 32 + lane);
        float4 c = __ldg(f4 + (size_t)s2 * 32 + lane);
        float4 d = __ldg(f4 + (size_t)s3 * 32 + lane);
        acc.x += (a.x + b.x) + (c.x + d.x);
        acc.y += (a.y + b.y) + (c.y + d.y);
        acc.z += (a.z + b.z) + (c.z + d.z);
        acc.w += (a.w + b.w) + (c.w + d.w);
    }
    for (; i < deg; i++) {
        int s0 = __ldg(g_nbr + start + i);
        float4 a = __ldg(f4 + (size_t)s0 * 32 + lane);
        acc.x += a.x; acc.y += a.y; acc.z += a.z; acc.w += a.w;
    }
    float inv = 1.0f / (float)max(deg, 1);
    acc.x *= inv; acc.y *= inv; acc.z *= inv; acc.w *= inv;
    reinterpret_cast<float4*>(g_agg)[(size_t)v * 32 + lane] = acc;
}

// ---------------------------------------------------------------------------
// Gather-mean bf16 (layer 2): reads g_h1b (half traffic), fp32 accumulate
// ---------------------------------------------------------------------------
__device__ __forceinline__ void add_bf16x4(float4& acc, uint2 p) {
    float2 a = __bfloat1622float2(*reinterpret_cast<__nv_bfloat162*>(&p.x));
    float2 b = __bfloat1622float2(*reinterpret_cast<__nv_bfloat162*>(&p.y));
    acc.x += a.x; acc.y += a.y; acc.z += b.x; acc.w += b.y;
}

__global__ void __launch_bounds__(256) gather_b16_kernel(int n)
{
    int v = (blockIdx.x * 256 + threadIdx.x) >> 5;
    int lane = threadIdx.x & 31;
    if (v >= n) return;
    int start = __ldg(g_off + NMAX + v);
    int deg   = __ldg(g_deg + NMAX + v);
    const int* nbr = g_nbr + EMAX;
    const uint2* f = reinterpret_cast<const uint2*>(g_h1b);
    float4 acc = make_float4(0.f, 0.f, 0.f, 0.f);
    int i = 0;
    for (; i + 4 <= deg; i += 4) {
        int s0 = __ldg(nbr + start + i);
        int s1 = __ldg(nbr + start + i + 1);
        int s2 = __ldg(nbr + start + i + 2);
        int s3 = __ldg(nbr + start + i + 3);
        uint2 p0 = __ldg(f + (size_t)s0 * 32 + lane);
        uint2 p1 = __ldg(f + (size_t)s1 * 32 + lane);
        uint2 p2 = __ldg(f + (size_t)s2 * 32 + lane);
        uint2 p3 = __ldg(f + (size_t)s3 * 32 + lane);
        add_bf16x4(acc, p0); add_bf16x4(acc, p1);
        add_bf16x4(acc, p2); add_bf16x4(acc, p3);
    }
    for (; i < deg; i++) {
        int s0 = __ldg(nbr + start + i);
        uint2 p0 = __ldg(f + (size_t)s0 * 32 + lane);
        add_bf16x4(acc, p0);
    }
    float inv = 1.0f / (float)max(deg, 1);
    acc.x *= inv; acc.y *= inv; acc.z *= inv; acc.w *= inv;
    reinterpret_cast<float4*>(g_agg)[(size_t)v * 32 + lane] = acc;
}

// ---------------------------------------------------------------------------
// HMMA SAGE layer (templated):
// MODE 0: out = g_h1 (fp32) + g_h1b (bf16 copy).  relu(agg@wl + xin@wr + b)
// MODE 1: layer-2 + fused head -> out = d_out [n,40].
//   After main GEMM, h2 fragments + h1 rows form a bf16 hi/lo [64 x 256]
//   cat-tile in smem; second HMMA GEMM (M64,N40,K256, 3 products) + b_out.
// ---------------------------------------------------------------------------
template <int MODE>
__global__ void __launch_bounds__(256) layer_mma_kernel(
    const float* __restrict__ xin, const float* __restrict__ bias,
    float* __restrict__ out, int n,
    const unsigned short* __restrict__ wth_base,
    const unsigned short* __restrict__ wtl_base,
    const float* __restrict__ b_out)
{
    extern __shared__ unsigned short sm[];
    unsigned short* s_ah = sm;                       // 64 x APAD
    unsigned short* s_al = sm + 64 * APAD;
    unsigned short* s_wh = sm + 2 * 64 * APAD;       // 128 x APAD
    unsigned short* s_wl = s_wh + 128 * APAD;

    int tid = threadIdx.x, wid = tid >> 5, lane = tid & 31;
    int r0 = blockIdx.x * 64;
    int mrow = (wid & 1) * 32;
    int ncol = (wid >> 1) * 32;
    int rq = lane >> 2;

    float acc[2][4][4];
#pragma unroll
    for (int mt = 0; mt < 2; mt++)
#pragma unroll
        for (int nt = 0; nt < 4; nt++)
#pragma unroll
            for (int q = 0; q < 4; q++) acc[mt][nt][q] = 0.f;

    for (int chunk = 0; chunk < 2; chunk++) {
        if (chunk) __syncthreads();   // protect smem reuse

        // ---- stage A (64 rows), fp32 -> bf16 hi/lo split ----
        const float4* src = (chunk == 0) ? reinterpret_cast<const float4*>(g_agg)
                                         : reinterpret_cast<const float4*>(xin);
#pragma unroll
        for (int i = 0; i < 8; i++) {
            int f = tid + i * 256;          // 64 rows * 32 float4
            int row = f >> 5, k4 = f & 31;
            int gr = r0 + row;
            if (gr >= n) gr = n - 1;
            float4 v = __ldg(src + (size_t)gr * 32 + k4);
            unsigned hp0, lp0, hp1, lp1;
            split_pack(v.x, v.y, hp0, lp0);
            split_pack(v.z, v.w, hp1, lp1);
            int o = row * APAD + k4 * 4;
            *reinterpret_cast<uint2*>(s_ah + o) = make_uint2(hp0, hp1);
            *reinterpret_cast<uint2*>(s_al + o) = make_uint2(lp0, lp1);
        }

        // ---- stage W chunk (pre-split transposed images) ----
        {
            const uint2* gh = reinterpret_cast<const uint2*>(wth_base) + chunk * 4096;
            const uint2* gl = reinterpret_cast<const uint2*>(wtl_base) + chunk * 4096;
#pragma unroll
            for (int i = 0; i < 16; i++) {
                int j = tid + i * 256;        // 128 rows * 32 uint2
                int nrow = j >> 5, kk = (j & 31) * 4;
                int o = nrow * APAD + kk;
                *reinterpret_cast<uint2*>(s_wh + o) = __ldg(gh + j);
                *reinterpret_cast<uint2*>(s_wl + o) = __ldg(gl + j);
            }
        }
        __syncthreads();

        // ---- compute: 8 k-steps of m16n8k16, 3 products ----
#pragma unroll
        for (int s = 0; s < 8; s++) {
            int kc = s * 16 + (lane & 3) * 2;
            unsigned bh[4][2], bl[4][2];
#pragma unroll
            for (int nt = 0; nt < 4; nt++) {
                int nn = ncol + nt * 8 + rq;
                bh[nt][0] = *reinterpret_cast<unsigned*>(s_wh + nn * APAD + kc);
                bh[nt][1] = *reinterpret_cast<unsigned*>(s_wh + nn * APAD + kc + 8);
                bl[nt][0] = *reinterpret_cast<unsigned*>(s_wl + nn * APAD + kc);
                bl[nt][1] = *reinterpret_cast<unsigned*>(s_wl + nn * APAD + kc + 8);
            }
#pragma unroll
            for (int mt = 0; mt < 2; mt++) {
                int rr = mrow + mt * 16 + rq;
                unsigned ah[4], al[4];
                ah[0] = *reinterpret_cast<unsigned*>(s_ah + rr * APAD + kc);
                ah[1] = *reinterpret_cast<unsigned*>(s_ah + (rr + 8) * APAD + kc);
                ah[2] = *reinterpret_cast<unsigned*>(s_ah + rr * APAD + kc + 8);
                ah[3] = *reinterpret_cast<unsigned*>(s_ah + (rr + 8) * APAD + kc + 8);
                al[0] = *reinterpret_cast<unsigned*>(s_al + rr * APAD + kc);
                al[1] = *reinterpret_cast<unsigned*>(s_al + (rr + 8) * APAD + kc);
                al[2] = *reinterpret_cast<unsigned*>(s_al + rr * APAD + kc + 8);
                al[3] = *reinterpret_cast<unsigned*>(s_al + (rr + 8) * APAD + kc + 8);
#pragma unroll
                for (int nt = 0; nt < 4; nt++) {
                    mma16816(acc[mt][nt], ah, bh[nt]);   // hi*hi
                    mma16816(acc[mt][nt], ah, bl[nt]);   // hi*lo
                    mma16816(acc[mt][nt], al, bh[nt]);   // lo*hi
                }
            }
        }
    }

    if (MODE == 0) {
        // ---- epilogue: bias + relu -> g_h1 (fp32) + g_h1b (bf16) ----
#pragma unroll
        for (int mt = 0; mt < 2; mt++) {
#pragma unroll
            for (int nt = 0; nt < 4; nt++) {
                int col = ncol + nt * 8 + (lane & 3) * 2;
                float bx = __ldg(bias + col), by = __ldg(bias + col + 1);
#pragma unroll
                for (int q2 = 0; q2 < 2; q2++) {
                    int row = r0 + mrow + mt * 16 + rq + q2 * 8;
                    if (row < n) {
                        float vx = fmaxf(acc[mt][nt][q2 * 2 + 0] + bx, 0.f);
                        float vy = fmaxf(acc[mt][nt][q2 * 2 + 1] + by, 0.f);
                        *reinterpret_cast<float2*>(out + (size_t)row * 128 + col)
                            = make_float2(vx, vy);
                        __nv_bfloat162 bb = __floats2bfloat162_rn(vx, vy);
                        *reinterpret_cast<unsigned*>(g_h1b + (size_t)row * 128 + col)
                            = *reinterpret_cast<unsigned*>(&bb);
                    }
                }
            }
        }
        return;
    }

    // ================= MODE 1: fused head =================
    __syncthreads();   // everyone done reading main-phase smem

    // head smem layout (overlays main): [s_hh 64x264][s_hl 64x264]
    //                                   [s_oh 40x264][s_ol 40x264]
    unsigned short* s_hh = sm;
    unsigned short* s_hl = sm + 64 * HPAD;           // 16896
    unsigned short* s_oh = sm + 2 * 64 * HPAD;       // 33792
    unsigned short* s_ol = s_oh + 40 * HPAD;

    // 1) store relu(h2)+bias fragments into cat-tile cols [128..256)
#pragma unroll
    for (int mt = 0; mt < 2; mt++) {
#pragma unroll
        for (int nt = 0; nt < 4; nt++) {
            int col = ncol + nt * 8 + (lane & 3) * 2;
            float bx = __ldg(bias + col), by = __ldg(bias + col + 1);
#pragma unroll
            for (int q2 = 0; q2 < 2; q2++) {
                int row = mrow + mt * 16 + rq + q2 * 8;
                float vx = fmaxf(acc[mt][nt][q2 * 2 + 0] + bx, 0.f);
                float vy = fmaxf(acc[mt][nt][q2 * 2 + 1] + by, 0.f);
                unsigned hp, lp;
                split_pack(vx, vy, hp, lp);
                int o = row * HPAD + 128 + col;
                *reinterpret_cast<unsigned*>(s_hh + o) = hp;
                *reinterpret_cast<unsigned*>(s_hl + o) = lp;
            }
        }
    }

    // 2) load h1 rows (fp32) into cat-tile cols [0..128)
    {
        const float4* h14 = reinterpret_cast<const float4*>(xin);  // xin == g_h1
#pragma unroll
        for (int i = 0; i < 8; i++) {
            int f = tid + i * 256;
            int row = f >> 5, k4 = f & 31;
            int gr = r0 + row;
            if (gr >= n) gr = n - 1;
            float4 v = __ldg(h14 + (size_t)gr * 32 + k4);
            unsigned hp0, lp0, hp1, lp1;
            split_pack(v.x, v.y, hp0, lp0);
            split_pack(v.z, v.w, hp1, lp1);
            int o = row * HPAD + k4 * 4;
            *reinterpret_cast<uint2*>(s_hh + o) = make_uint2(hp0, hp1);
            *reinterpret_cast<uint2*>(s_hl + o) = make_uint2(lp0, lp1);
        }
    }

    // 3) stage w_out images [40 x 256] hi/lo
    {
        const uint2* gh = reinterpret_cast<const uint2*>(g_woth);
        const uint2* gl = reinterpret_cast<const uint2*>(g_wotl);
#pragma unroll
        for (int i = 0; i < 10; i++) {
            int j = tid + i * 256;            // 40*64 = 2560
            if (j < 2560) {
                int nn = j >> 6, kk = (j & 63) * 4;
                int o = nn * HPAD + kk;
                *reinterpret_cast<uint2*>(s_oh + o) = __ldg(gh + j);
                *reinterpret_cast<uint2*>(s_ol + o) = __ldg(gl + j);
            }
        }
    }
    __syncthreads();

    // 4) head GEMM: warp wg = wid>>1 covers n-tile wg (+ tile 4 if wg==0)
    int wg = wid >> 1;
    int mrow2 = (wid & 1) * 32;
    int nts0 = wg, nts1 = 4;
    int nnt = (wg == 0) ? 2 : 1;

    float acc2[2][2][4];
#pragma unroll
    for (int mt = 0; mt < 2; mt++)
#pragma unroll
        for (int t = 0; t < 2; t++)
#pragma unroll
            for (int q = 0; q < 4; q++) acc2[mt][t][q] = 0.f;

#pragma unroll
    for (int s = 0; s < 16; s++) {
        int kc = s * 16 + (lane & 3) * 2;
        unsigned bh[2][2], bl[2][2];
        for (int t = 0; t < nnt; t++) {
            int nt = t ? nts1 : nts0;
            int nn = nt * 8 + rq;
            bh[t][0] = *reinterpret_cast<unsigned*>(s_oh + nn * HPAD + kc);
            bh[t][1] = *reinterpret_cast<unsigned*>(s_oh + nn * HPAD + kc + 8);
            bl[t][0] = *reinterpret_cast<unsigned*>(s_ol + nn * HPAD + kc);
            bl[t][1] = *reinterpret_cast<unsigned*>(s_ol + nn * HPAD + kc + 8);
        }
#pragma unroll
        for (int mt = 0; mt < 2; mt++) {
            int rr = mrow2 + mt * 16 + rq;
            unsigned ah[4], al[4];
            ah[0] = *reinterpret_cast<unsigned*>(s_hh + rr * HPAD + kc);
            ah[1] = *reinterpret_cast<unsigned*>(s_hh + (rr + 8) * HPAD + kc);
            ah[2] = *reinterpret_cast<unsigned*>(s_hh + rr * HPAD + kc + 8);
            ah[3] = *reinterpret_cast<unsigned*>(s_hh + (rr + 8) * HPAD + kc + 8);
            al[0] = *reinterpret_cast<unsigned*>(s_hl + rr * HPAD + kc);
            al[1] = *reinterpret_cast<unsigned*>(s_hl + (rr + 8) * HPAD + kc);
            al[2] = *reinterpret_cast<unsigned*>(s_hl + rr * HPAD + kc + 8);
            al[3] = *reinterpret_cast<unsigned*>(s_hl + (rr + 8) * HPAD + kc + 8);
            for (int t = 0; t < nnt; t++) {
                mma16816(acc2[mt][t], ah, bh[t]);
                mma16816(acc2[mt][t], ah, bl[t]);
                mma16816(acc2[mt][t], al, bh[t]);
            }
        }
    }

    // 5) write d_out
#pragma unroll
    for (int mt = 0; mt < 2; mt++) {
        for (int t = 0; t < nnt; t++) {
            int nt = t ? nts1 : nts0;
            int col = nt * 8 + (lane & 3) * 2;
            float bx = __ldg(b_out + col), by = __ldg(b_out + col + 1);
#pragma unroll
            for (int q2 = 0; q2 < 2; q2++) {
                int row = r0 + mrow2 + mt * 16 + rq + q2 * 8;
                if (row < n) {
                    float2 o = make_float2(acc2[mt][t][q2 * 2 + 0] + bx,
                                           acc2[mt][t][q2 * 2 + 1] + by);
                    *reinterpret_cast<float2*>(out + (size_t)row * 40 + col) = o;
                }
            }
        }
    }
}

// ---------------------------------------------------------------------------
extern "C" void kernel_launch(void* const* d_in, const int* in_sizes, int n_in,
                              void* d_out, int out_size)
{
    const float* x     = (const float*)d_in[0];
    const int*   ei1   = (const int*)d_in[1];
    const int*   ei2   = (const int*)d_in[2];
    const float* wl1   = (const float*)d_in[3];
    const float* wr1   = (const float*)d_in[4];
    const float* b1    = (const float*)d_in[5];
    const float* wl2   = (const float*)d_in[6];
    const float* wr2   = (const float*)d_in[7];
    const float* b2    = (const float*)d_in[8];
    const float* w_out = (const float*)d_in[9];
    const float* b_out = (const float*)d_in[10];

    int n  = in_sizes[0] / D;
    int E1 = in_sizes[1] / 2;
    int E2 = in_sizes[2] / 2;

    void *p_h1 = nullptr, *p_wth = nullptr, *p_wtl = nullptr;
    cudaGetSymbolAddress(&p_h1, g_h1);
    cudaGetSymbolAddress(&p_wth, g_wth);
    cudaGetSymbolAddress(&p_wtl, g_wtl);
    float* h1 = (float*)p_h1;
    const unsigned short* wth = (const unsigned short*)p_wth;
    const unsigned short* wtl = (const unsigned short*)p_wtl;

    const int LAYER_SMEM = 2 * 64 * HPAD * 2 + 2 * 40 * HPAD * 2;  // 109824 B
    cudaFuncSetAttribute(layer_mma_kernel<0>,
                         cudaFuncAttributeMaxDynamicSharedMemorySize, LAYER_SMEM);
    cudaFuncSetAttribute(layer_mma_kernel<1>,
                         cudaFuncAttributeMaxDynamicSharedMemorySize, LAYER_SMEM);

    int nb_scan = (n + 1023) / 1024;

    // ---- prep + CSR build ----
    prep_zero_kernel<<<296, 256>>>(wl1, wr1, wl2, wr2, w_out);
    count_both_kernel<<<(E1 + E2 + 255) / 256, 256>>>(ei1, ei2, E1, E2);
    scan1_kernel<<<dim3(nb_scan, 2), 1024>>>(n);
    scan2_kernel<<<2, 1024>>>(nb_scan);
    scan3_kernel<<<dim3((n + 255) / 256, 2), 256>>>(n);
    fill_both_kernel<<<(E1 + E2 + 255) / 256, 256>>>(ei1, ei2, E1, E2);

    int layer_blocks = (n + 63) / 64;
    int gather_blocks = (n * 32 + 255) / 256;

    // ---- layer 1 ----
    gather_f32_kernel<<<gather_blocks, 256>>>(x, n);
    layer_mma_kernel<0><<<layer_blocks, 256, LAYER_SMEM>>>(
        x, b1, h1, n, wth, wtl, b_out);

    // ---- layer 2 + fused head ----
    gather_b16_kernel<<<gather_blocks, 256>>>(n);
    layer_mma_kernel<1><<<layer_blocks, 256, LAYER_SMEM>>>(
        h1, b2, (float*)d_out, n, wth + 32768, wtl + 32768, b_out);
}